// round 4
// baseline (speedup 1.0000x reference)
#include <cuda_runtime.h>
#include <math.h>

#define S 192
#define HD 64
#define NHEAD 8
#define SS (S*S)

// Output layout (concatenated flattened tuple, reference return order):
//   z:      [1,8,192,64]        offset 0
//   score:  [1,8,192,192,192]   offset 98304
//   vgated: [1,8,192,192,64]    offset 56721408
//   M:      [1,8,192]           offset 75595776
#define Z_OFF      0u
#define SCORE_OFF  98304u
#define VG_OFF     56721408u
#define M_OFF      75595776u

// scratch for the big writers only (z path is self-contained)
__device__ float g_qk[NHEAD * SS];      // [n][t][q] = k2[t].q[q]
__device__ float g_kk[NHEAD * SS];      // [n][s][t] = k1[s].k2[t]
__device__ float g_sv1[NHEAD * S * HD]; // silu(v1)

// ---------------- silu(v1) --------------------------------------------------
__global__ void silu_kernel(const float* __restrict__ v1) {
    int i = blockIdx.x * blockDim.x + threadIdx.x;
    if (i < NHEAD * S * HD) {
        float x = v1[i];
        g_sv1[i] = x / (1.0f + expf(-x));
    }
}

// ---------------- C[n][i][j] = dot(A[n][i][:], B[n][j][:]) ------------------
__global__ void gemm_abt_kernel(const float* __restrict__ A,
                                const float* __restrict__ B,
                                float* __restrict__ C) {
    __shared__ float As[16][65];
    __shared__ float Bs[16][65];
    int n = blockIdx.z;
    int i0 = blockIdx.y * 16, j0 = blockIdx.x * 16;
    int tid = threadIdx.y * 16 + threadIdx.x;
    for (int idx = tid; idx < 16 * HD; idx += 256) {
        int r = idx >> 6, c = idx & 63;
        As[r][c] = A[(n * S + i0 + r) * HD + c];
        Bs[r][c] = B[(n * S + j0 + r) * HD + c];
    }
    __syncthreads();
    float acc = 0.0f;
#pragma unroll
    for (int k = 0; k < HD; k++) acc += As[threadIdx.y][k] * Bs[threadIdx.x][k];
    C[(n * S + i0 + threadIdx.y) * S + j0 + threadIdx.x] = acc;
}

// ---------------- fully fused z + M, one block per head ---------------------
// Self-contained: computes kk, column stats, U, qk, softmax, z, M from raw
// inputs (only external dependency: g_sv1 from silu_kernel).
// Dynamic smem (floats):
//   K  [0, 36864)        kk -> expB, then qk -> A  (reused)
//   U  [36864, 49152)    U[t*64+h]
//   Cc [49152, 49344)    sum_{s<=t} exp(0.125*kk[s,t])
//   mk [49344, 49536)    max_{s<=t} kk[s,t]  (raw)
//   mq [49536, 49728)    M0 per q (scaled)
//   Dq [49728, 49920)    softmax denom per q
//   As [49920, 51008)    16x68 tile
//   Bs [51008, 52096)    16x68 tile
// total 52096 floats = 208384 bytes
#define FZ_SMEM_FLOATS 52096

__global__ void fused_zM_kernel(const float* __restrict__ k1,
                                const float* __restrict__ k2,
                                const float* __restrict__ qin,
                                const float* __restrict__ v2,
                                float* __restrict__ outZ,
                                float* __restrict__ outM) {
    extern __shared__ float sm[];
    float* K  = sm;
    float* U  = sm + 36864;
    float* Cc = sm + 49152;
    float* mk = sm + 49344;
    float* mq = sm + 49536;
    float* Dq = sm + 49728;
    float* As = sm + 49920;
    float* Bs = sm + 51008;

    int n = blockIdx.x;
    int tid = threadIdx.x;            // 256 threads
    int ty = tid >> 4, tx = tid & 15;
    const float* k1h = k1 + n * S * HD;
    const float* k2h = k2 + n * S * HD;
    const float* qh  = qin + n * S * HD;
    const float* v2h = v2 + n * S * HD;

    // ---- Phase 1: K[s*S+t] = k1[s] . k2[t]
    for (int i0 = 0; i0 < S; i0 += 16) {
        for (int j0 = 0; j0 < S; j0 += 16) {
            for (int l = tid; l < 16 * HD; l += 256) {
                int r = l >> 6, c = l & 63;
                As[r * 68 + c] = k1h[(i0 + r) * HD + c];
                Bs[r * 68 + c] = k2h[(j0 + r) * HD + c];
            }
            __syncthreads();
            float acc = 0.0f;
#pragma unroll
            for (int c = 0; c < HD; c++) acc += As[ty * 68 + c] * Bs[tx * 68 + c];
            K[(i0 + ty) * S + (j0 + tx)] = acc;
            __syncthreads();
        }
    }

    // ---- Phase 2: per-t stats on raw kk (s <= t)
    if (tid < S) {
        int t = tid;
        float m = -INFINITY, c = 0.0f;
        for (int s = 0; s <= t; s++) {
            float v = K[s * S + t];
            m = fmaxf(m, v);
            c += expf(0.125f * v);
        }
        mk[t] = m;
        Cc[t] = c;
    }
    __syncthreads();

    // ---- Phase 3: K := expB (exp(0.125*kk) for s<=t else 0)
    for (int idx = tid; idx < SS; idx += 256) {
        int s = idx / S, t = idx - s * S;
        float v = K[idx];
        K[idx] = (s <= t) ? expf(0.125f * v) : 0.0f;
    }
    __syncthreads();

    // ---- Phase 4: U[t*64+h] = v2[t,h] * sum_{s<=t} expB[s,t]*sv1[s,h]
    for (int idx = tid; idx < S * HD; idx += 256) {
        int t = idx >> 6, h = idx & 63;
        float acc = 0.0f;
        for (int s = 0; s <= t; s++)
            acc += K[s * S + t] * g_sv1[(n * S + s) * HD + h];
        U[idx] = acc * v2h[t * HD + h];
    }
    __syncthreads();

    // ---- Phase 5: K[t*S+q] = k2[t] . q[q]   (overwrites expB)
    for (int i0 = 0; i0 < S; i0 += 16) {
        for (int j0 = 0; j0 < S; j0 += 16) {
            for (int l = tid; l < 16 * HD; l += 256) {
                int r = l >> 6, c = l & 63;
                As[r * 68 + c] = k2h[(i0 + r) * HD + c];
                Bs[r * 68 + c] = qh[(j0 + r) * HD + c];
            }
            __syncthreads();
            float acc = 0.0f;
#pragma unroll
            for (int c = 0; c < HD; c++) acc += As[ty * 68 + c] * Bs[tx * 68 + c];
            K[(i0 + ty) * S + (j0 + tx)] = acc;
            __syncthreads();
        }
    }

    // ---- Phase 6: mq[q] = M0 = max_{t<=q} 0.125*(qk[t,q] + mk[t])
    if (tid < S) {
        int qq = tid;
        float m = -INFINITY;
        for (int t = 0; t <= qq; t++)
            m = fmaxf(m, 0.125f * (K[t * S + qq] + mk[t]));
        mq[qq] = m;
    }
    __syncthreads();

    // ---- Phase 7: K := A = exp(0.125*qk - M0[q]) for t<=q else 0
    for (int idx = tid; idx < SS; idx += 256) {
        int t = idx / S, qc = idx - t * S;
        float v = K[idx];
        K[idx] = (t <= qc) ? expf(0.125f * v - mq[qc]) : 0.0f;
    }
    __syncthreads();

    // ---- Phase 8: D[q] = sum_t A[t,q]*Cc[t];  M = M0 + log(D + 0.01)
    if (tid < S) {
        int qq = tid;
        float d = 0.0f;
        for (int t = 0; t <= qq; t++) d += K[t * S + qq] * Cc[t];
        Dq[qq] = d;
        outM[n * S + qq] = mq[qq] + logf(d + 0.01f);
    }
    __syncthreads();

    // ---- Phase 9: z[q,h] = (1/D[q]) * sum_t A[t,q]*U[t,h]
    for (int idx = tid; idx < S * HD; idx += 256) {
        int qq = idx >> 6, h = idx & 63;
        float acc = 0.0f;
        for (int t = 0; t <= qq; t++)
            acc += K[t * S + qq] * U[t * HD + h];
        outZ[(n * S + qq) * HD + h] = acc / Dq[qq];
    }
}

// ------- score[n][s][t][q] = mask ? -1e6 : kk[s,t]+qk[t,q]  (226 MB store) --
__global__ void score_kernel(float* __restrict__ out) {
    unsigned i = blockIdx.x * blockDim.x + threadIdx.x;  // < NHEAD*S*S*48
    int q4 = i % 48;
    unsigned row = i / 48;
    int t = row % S;
    unsigned r2 = row / S;
    int s = r2 % S;
    int n = r2 / S;
    float kkv = g_kk[(n * S + s) * S + t];
    float4 qv = reinterpret_cast<const float4*>(g_qk)[(n * S + t) * 48 + q4];
    int q0 = q4 * 4;
    bool rowmask = (s > t);
    float4 o;
    o.x = (rowmask || t > q0)     ? -1000000.0f : kkv + qv.x;
    o.y = (rowmask || t > q0 + 1) ? -1000000.0f : kkv + qv.y;
    o.z = (rowmask || t > q0 + 2) ? -1000000.0f : kkv + qv.z;
    o.w = (rowmask || t > q0 + 3) ? -1000000.0f : kkv + qv.w;
    reinterpret_cast<float4*>(out)[i] = o;
}

// ------- vgated[n][s][t][h] = sv1[s,h]*v2[t,h]  (75 MB store) ---------------
__global__ void vgated_kernel(float* __restrict__ out, const float* __restrict__ v2) {
    unsigned i = blockIdx.x * blockDim.x + threadIdx.x;  // < NHEAD*S*S*16
    int h4 = i % 16;
    unsigned row = i / 16;
    int t = row % S;
    unsigned r2 = row / S;
    int s = r2 % S;
    int n = r2 / S;
    float4 a = reinterpret_cast<const float4*>(g_sv1)[(n * S + s) * 16 + h4];
    float4 b = reinterpret_cast<const float4*>(v2)[(n * S + t) * 16 + h4];
    float4 o;
    o.x = a.x * b.x;
    o.y = a.y * b.y;
    o.z = a.z * b.z;
    o.w = a.w * b.w;
    reinterpret_cast<float4*>(out)[i] = o;
}

extern "C" void kernel_launch(void* const* d_in, const int* in_sizes, int n_in,
                              void* d_out, int out_size) {
    // setup_inputs insertion order: q, k1, k2, v1, v2
    const float* q  = (const float*)d_in[0];
    const float* k1 = (const float*)d_in[1];
    const float* k2 = (const float*)d_in[2];
    const float* v1 = (const float*)d_in[3];
    const float* v2 = (const float*)d_in[4];
    float* out = (float*)d_out;

    cudaFuncSetAttribute(fused_zM_kernel,
                         cudaFuncAttributeMaxDynamicSharedMemorySize,
                         FZ_SMEM_FLOATS * sizeof(float));

    // 1. silu(v1) -> g_sv1
    silu_kernel<<<(NHEAD * S * HD + 255) / 256, 256>>>(v1);

    // 2. scratch for the big writers
    {
        dim3 b(16, 16), g(S / 16, S / 16, NHEAD);
        gemm_abt_kernel<<<g, b>>>(k2, q, g_qk);   // g_qk[t][q]
        gemm_abt_kernel<<<g, b>>>(k1, k2, g_kk);  // g_kk[s][t]
    }

    // 3. fused z + M (self-contained; depends only on g_sv1)
    fused_zM_kernel<<<NHEAD, 256, FZ_SMEM_FLOATS * sizeof(float)>>>(
        k1, k2, q, v2, out + Z_OFF, out + M_OFF);

    // 4. big broadcast writes
    score_kernel<<<(NHEAD * S * S * 48) / 256, 256>>>(out + SCORE_OFF);
    vgated_kernel<<<(NHEAD * S * S * 16) / 256, 256>>>(out + VG_OFF, v2);
}

// round 6
// speedup vs baseline: 2.6972x; 2.6972x over previous
#include <cuda_runtime.h>
#include <math.h>

#define S 192
#define HD 64
#define NHEAD 8
#define SS (S*S)

// Output layout (concatenated flattened tuple, reference return order):
//   z:      [1,8,192,64]        offset 0
//   score:  [1,8,192,192,192]   offset 98304
//   vgated: [1,8,192,192,64]    offset 56721408
//   M:      [1,8,192]           offset 75595776
#define Z_OFF      0u
#define SCORE_OFF  98304u
#define VG_OFF     56721408u
#define M_OFF      75595776u

// scratch (device globals; no allocation allowed)
__device__ float g_qk[NHEAD * SS];      // [n][t][q] = k2[t].q[q]   (score only)
__device__ float g_kk[NHEAD * SS];      // [n][s][t] = k1[s].k2[t]  (score only)
__device__ float g_sv1[NHEAD * S * HD]; // silu(v1)                 (proven handoff)

// ---------------- silu(v1) --------------------------------------------------
__global__ void silu_kernel(const float* __restrict__ v1) {
    int i = blockIdx.x * blockDim.x + threadIdx.x;
    if (i < NHEAD * S * HD) {
        float x = v1[i];
        g_sv1[i] = x / (1.0f + expf(-x));
    }
}

// ---------------- C[n][i][j] = dot(A[n][i][:], B[n][j][:]) ------------------
__global__ void gemm_abt_kernel(const float* __restrict__ A,
                                const float* __restrict__ B,
                                float* __restrict__ C) {
    __shared__ float As[16][65];
    __shared__ float Bs[16][65];
    int n = blockIdx.z;
    int i0 = blockIdx.y * 16, j0 = blockIdx.x * 16;
    int tid = threadIdx.y * 16 + threadIdx.x;
    for (int idx = tid; idx < 16 * HD; idx += 256) {
        int r = idx >> 6, c = idx & 63;
        As[r][c] = A[(n * S + i0 + r) * HD + c];
        Bs[r][c] = B[(n * S + j0 + r) * HD + c];
    }
    __syncthreads();
    float acc = 0.0f;
#pragma unroll
    for (int k = 0; k < HD; k++) acc += As[threadIdx.y][k] * Bs[threadIdx.x][k];
    C[(n * S + i0 + threadIdx.y) * S + j0 + threadIdx.x] = acc;
}

// ---------------- z + M: SELF-CONTAINED, one block per (head, q-tile) -------
// Computes everything from raw k1,k2,q,v2 + g_sv1. No g_qk/g_kk reads.
// Block (qt, n), qmax = qt*16+15, T = qmax+1.
// smem float offsets:
//   K   0      (36864)  kk[s*S+t] -> expB in place
//   U   36864  (12288)  U[t*64+h]
//   Cc  49152  (192)
//   mk  49344  (192)
//   mq  49536  (16)
//   Dq  49552  (16)
//   Qt  49568  (3264)   qk tile [t*17+ql] -> A in place
//   As  52832  (1088)   16x68 stage
//   Bs  53920  (1088)   16x68 / 16x64 stage
#define ZQ_SMEM_FLOATS 55008

__global__ void zq_kernel(const float* __restrict__ k1,
                          const float* __restrict__ k2,
                          const float* __restrict__ qin,
                          const float* __restrict__ v2,
                          float* __restrict__ outZ,
                          float* __restrict__ outM) {
    extern __shared__ float sm[];
    float* K  = sm;
    float* U  = sm + 36864;
    float* Cc = sm + 49152;
    float* mk = sm + 49344;
    float* mq = sm + 49536;
    float* Dq = sm + 49552;
    float* Qt = sm + 49568;
    float* As = sm + 52832;
    float* Bs = sm + 53920;
    float4* As4 = reinterpret_cast<float4*>(As);
    float4* Bs4 = reinterpret_cast<float4*>(Bs);

    int qt = blockIdx.x;
    int n  = blockIdx.y;
    int qmax = qt * 16 + 15;
    int T = qmax + 1;
    int tid = threadIdx.x;           // 256
    int ty = tid >> 4, tx = tid & 15;
    const float* k1h = k1 + n * S * HD;
    const float* k2h = k2 + n * S * HD;
    const float* qh  = qin + n * S * HD;
    const float* v2h = v2 + n * S * HD;
    const float* svh = g_sv1 + n * S * HD;

    // ---- P1: K[s*S+t] = k1[s].k2[t] for tiles j0 >= i0 (covers s<=t)
    for (int i0 = 0; i0 < T; i0 += 16) {
        for (int j0 = i0; j0 < T; j0 += 16) {
            __syncthreads();
            {   // stage 16x64 each, float4, one per thread
                int r = tid >> 4, c4 = tid & 15;
                As4[r * 17 + c4] = reinterpret_cast<const float4*>(k1h + (i0 + r) * HD)[c4];
                Bs4[r * 17 + c4] = reinterpret_cast<const float4*>(k2h + (j0 + r) * HD)[c4];
            }
            __syncthreads();
            float acc = 0.0f;
#pragma unroll
            for (int c = 0; c < HD; c++) acc += As[ty * 68 + c] * Bs[tx * 68 + c];
            K[(i0 + ty) * S + (j0 + tx)] = acc;
        }
    }
    __syncthreads();

    // ---- P2a: raw max per t (s<=t)
    if (tid < T) {
        int t = tid;
        float m = -INFINITY;
        for (int s = 0; s <= t; s++) m = fmaxf(m, K[s * S + t]);
        mk[t] = m;
    }
    __syncthreads();

    // ---- P3: K := expB (exp(0.125*kk) if s<=t else 0), all s,t < T
    for (int idx = tid; idx < T * T; idx += 256) {
        int s = idx / T, t = idx - s * T;
        int a = s * S + t;
        K[a] = (s <= t) ? expf(0.125f * K[a]) : 0.0f;
    }
    __syncthreads();

    // ---- P2b: Cc[t] = sum_s expB[s,t]
    if (tid < T) {
        int t = tid;
        float c = 0.0f;
        for (int s = 0; s <= t; s++) c += K[s * S + t];
        Cc[t] = c;
    }
    __syncthreads();

    // ---- P4: U[t,h] = v2[t,h] * sum_s expB[s,t]*sv1[s,h]  (staged GEMM)
    for (int t0 = 0; t0 < T; t0 += 16) {
        float a0 = 0.f, a1 = 0.f, a2 = 0.f, a3 = 0.f;
        for (int s0 = 0; s0 <= t0; s0 += 16) {
            __syncthreads();
            // stage sv1 16x64 tile (stride 64, contiguous): one float4/thread
            Bs4[tid] = reinterpret_cast<const float4*>(svh + (s0 + tid * 4 / HD) * HD)[(tid * 4 % HD) / 4];
            __syncthreads();
#pragma unroll
            for (int c = 0; c < 16; c++) {
                float e = K[(s0 + c) * S + (t0 + ty)];
                a0 += e * Bs[c * 64 + tx];
                a1 += e * Bs[c * 64 + tx + 16];
                a2 += e * Bs[c * 64 + tx + 32];
                a3 += e * Bs[c * 64 + tx + 48];
            }
        }
        const float* vv = v2h + (t0 + ty) * HD + tx;
        float* uu = U + (t0 + ty) * HD + tx;
        uu[0]  = a0 * vv[0];
        uu[16] = a1 * vv[16];
        uu[32] = a2 * vv[32];
        uu[48] = a3 * vv[48];
    }
    __syncthreads();

    // ---- P5: Qt[t*17+ql] = k2[t].q[qt*16+ql]
    for (int i0 = 0; i0 < T; i0 += 16) {
        __syncthreads();
        {
            int r = tid >> 4, c4 = tid & 15;
            As4[r * 17 + c4] = reinterpret_cast<const float4*>(k2h + (i0 + r) * HD)[c4];
            Bs4[r * 17 + c4] = reinterpret_cast<const float4*>(qh + (qt * 16 + r) * HD)[c4];
        }
        __syncthreads();
        float acc = 0.0f;
#pragma unroll
        for (int c = 0; c < HD; c++) acc += As[ty * 68 + c] * Bs[tx * 68 + c];
        Qt[(i0 + ty) * 17 + tx] = acc;
    }
    __syncthreads();

    // ---- P6: mq[ql] = max_{t<=q} 0.125*(qk[t,q] + mk[t])
    if (tid < 16) {
        int q = qt * 16 + tid;
        float m = -INFINITY;
        for (int t = 0; t <= q; t++)
            m = fmaxf(m, 0.125f * (Qt[t * 17 + tid] + mk[t]));
        mq[tid] = m;
    }
    __syncthreads();

    // ---- P7: Qt := A = exp(0.125*qk - mq) if t<=q else 0  (in place)
    for (int idx = tid; idx < T * 16; idx += 256) {
        int t = idx >> 4, ql = idx & 15;
        int q = qt * 16 + ql;
        float v = Qt[t * 17 + ql];
        Qt[t * 17 + ql] = (t <= q) ? expf(0.125f * v - mq[ql]) : 0.0f;
    }
    __syncthreads();

    // ---- P8: D[ql] = sum_t A*Cc ;  M = mq + log(D+0.01)
    if (tid < 16) {
        int q = qt * 16 + tid;
        float d = 0.0f;
        for (int t = 0; t <= q; t++) d += Qt[t * 17 + tid] * Cc[t];
        Dq[tid] = d;
        outM[n * S + q] = mq[tid] + logf(d + 0.01f);
    }
    __syncthreads();

    // ---- P9: z[q,h] = (1/D) * sum_t A[t,ql]*U[t,h]
    {
        int ql = ty, h = tx;
        int q = qt * 16 + ql;
        float a0 = 0.f, a1 = 0.f, a2 = 0.f, a3 = 0.f;
        for (int t = 0; t <= q; t++) {
            float a = Qt[t * 17 + ql];
            const float* uu = U + t * HD + h;
            a0 += a * uu[0];
            a1 += a * uu[16];
            a2 += a * uu[32];
            a3 += a * uu[48];
        }
        float inv = 1.0f / Dq[ql];
        float* zz = outZ + (n * S + q) * HD + h;
        zz[0]  = a0 * inv;
        zz[16] = a1 * inv;
        zz[32] = a2 * inv;
        zz[48] = a3 * inv;
    }
}

// ------- score[n][s][t][q] = mask ? -1e6 : kk[s,t]+qk[t,q]  (226 MB store) --
__global__ void score_kernel(float* __restrict__ out) {
    unsigned i = blockIdx.x * blockDim.x + threadIdx.x;  // < NHEAD*S*S*48
    int q4 = i % 48;
    unsigned row = i / 48;
    int t = row % S;
    unsigned r2 = row / S;
    int s = r2 % S;
    int n = r2 / S;
    float kkv = g_kk[(n * S + s) * S + t];
    float4 qv = reinterpret_cast<const float4*>(g_qk)[(n * S + t) * 48 + q4];
    int q0 = q4 * 4;
    bool rowmask = (s > t);
    float4 o;
    o.x = (rowmask || t > q0)     ? -1000000.0f : kkv + qv.x;
    o.y = (rowmask || t > q0 + 1) ? -1000000.0f : kkv + qv.y;
    o.z = (rowmask || t > q0 + 2) ? -1000000.0f : kkv + qv.z;
    o.w = (rowmask || t > q0 + 3) ? -1000000.0f : kkv + qv.w;
    reinterpret_cast<float4*>(out)[i] = o;
}

// ------- vgated[n][s][t][h] = sv1[s,h]*v2[t,h]  (75 MB store) ---------------
__global__ void vgated_kernel(float* __restrict__ out, const float* __restrict__ v2) {
    unsigned i = blockIdx.x * blockDim.x + threadIdx.x;  // < NHEAD*S*S*16
    int h4 = i % 16;
    unsigned row = i / 16;
    int t = row % S;
    unsigned r2 = row / S;
    int s = r2 % S;
    int n = r2 / S;
    float4 a = reinterpret_cast<const float4*>(g_sv1)[(n * S + s) * 16 + h4];
    float4 b = reinterpret_cast<const float4*>(v2)[(n * S + t) * 16 + h4];
    float4 o;
    o.x = a.x * b.x;
    o.y = a.y * b.y;
    o.z = a.z * b.z;
    o.w = a.w * b.w;
    reinterpret_cast<float4*>(out)[i] = o;
}

extern "C" void kernel_launch(void* const* d_in, const int* in_sizes, int n_in,
                              void* d_out, int out_size) {
    // setup_inputs insertion order: q, k1, k2, v1, v2  (proven in R4)
    const float* q  = (const float*)d_in[0];
    const float* k1 = (const float*)d_in[1];
    const float* k2 = (const float*)d_in[2];
    const float* v1 = (const float*)d_in[3];
    const float* v2 = (const float*)d_in[4];
    float* out = (float*)d_out;

    cudaFuncSetAttribute(zq_kernel,
                         cudaFuncAttributeMaxDynamicSharedMemorySize,
                         ZQ_SMEM_FLOATS * sizeof(float));

    // 1. silu(v1) -> g_sv1
    silu_kernel<<<(NHEAD * S * HD + 255) / 256, 256>>>(v1);

    // 2. z + M: self-contained, 96 blocks (12 q-tiles x 8 heads)
    {
        dim3 g(12, NHEAD);
        zq_kernel<<<g, 256, ZQ_SMEM_FLOATS * sizeof(float)>>>(
            k1, k2, q, v2, out + Z_OFF, out + M_OFF);
    }

    // 3. qk/kk scratch for score (proven handoff)
    {
        dim3 b(16, 16), g(S / 16, S / 16, NHEAD);
        gemm_abt_kernel<<<g, b>>>(k2, q, g_qk);
        gemm_abt_kernel<<<g, b>>>(k1, k2, g_kk);
    }

    // 4. big broadcast writes
    score_kernel<<<(NHEAD * S * S * 48) / 256, 256>>>(out + SCORE_OFF);
    vgated_kernel<<<(NHEAD * S * S * 16) / 256, 256>>>(out + VG_OFF, v2);
}

// round 7
// speedup vs baseline: 4.0453x; 1.4998x over previous
#include <cuda_runtime.h>
#include <math.h>

#define S 192
#define HD 64
#define NHEAD 8
#define SS (S*S)

// Output layout (concatenated flattened tuple, reference return order):
#define Z_OFF      0u
#define SCORE_OFF  98304u
#define VG_OFF     56721408u
#define M_OFF      75595776u

// scratch (device globals; no allocation allowed)
__device__ float g_qk[NHEAD * SS];      // [n][t][q] (score only)
__device__ float g_kk[NHEAD * SS];      // [n][s][t] (score only)
__device__ float g_sv1[NHEAD * S * HD]; // silu(v1)  (proven handoff)

// ---------------- silu(v1) --------------------------------------------------
__global__ void silu_kernel(const float* __restrict__ v1) {
    int i = blockIdx.x * blockDim.x + threadIdx.x;
    if (i < NHEAD * S * HD) {
        float x = v1[i];
        g_sv1[i] = x / (1.0f + expf(-x));
    }
}

// ------- C[n][i][j] = dot(A[n][i][:], B[n][j][:]) ; 32x32 tile, 2x2/thread --
__global__ void gemm_abt_kernel(const float* __restrict__ A,
                                const float* __restrict__ B,
                                float* __restrict__ C) {
    __shared__ float4 As4[32 * 17];
    __shared__ float4 Bs4[32 * 17];
    int n = blockIdx.z;
    int i0 = blockIdx.y * 32, j0 = blockIdx.x * 32;
    int tid = threadIdx.x;               // 256
    int ty = tid >> 4, tx = tid & 15;
    const float* Ah = A + (n * S + i0) * HD;
    const float* Bh = B + (n * S + j0) * HD;
#pragma unroll
    for (int k = 0; k < 2; k++) {
        int idx = tid + k * 256;         // 512 float4 per array
        int r = idx >> 4, c4 = idx & 15;
        As4[r * 17 + c4] = reinterpret_cast<const float4*>(Ah + r * HD)[c4];
        Bs4[r * 17 + c4] = reinterpret_cast<const float4*>(Bh + r * HD)[c4];
    }
    __syncthreads();
    float a00 = 0.f, a01 = 0.f, a10 = 0.f, a11 = 0.f;
#pragma unroll
    for (int k4 = 0; k4 < 16; k4++) {
        float4 p0 = As4[ty * 17 + k4];
        float4 p1 = As4[(ty + 16) * 17 + k4];
        float4 q0 = Bs4[tx * 17 + k4];
        float4 q1 = Bs4[(tx + 16) * 17 + k4];
        a00 += p0.x*q0.x + p0.y*q0.y + p0.z*q0.z + p0.w*q0.w;
        a01 += p0.x*q1.x + p0.y*q1.y + p0.z*q1.z + p0.w*q1.w;
        a10 += p1.x*q0.x + p1.y*q0.y + p1.z*q0.z + p1.w*q0.w;
        a11 += p1.x*q1.x + p1.y*q1.y + p1.z*q1.z + p1.w*q1.w;
    }
    float* Cr = C + n * SS;
    Cr[(i0 + ty) * S + j0 + tx]           = a00;
    Cr[(i0 + ty) * S + j0 + tx + 16]      = a01;
    Cr[(i0 + ty + 16) * S + j0 + tx]      = a10;
    Cr[(i0 + ty + 16) * S + j0 + tx + 16] = a11;
}

// ---------------- z + M: SELF-CONTAINED, flash-style streaming --------------
// Block (qt, n), T = qt*16+16. No kk triangle stored.
// smem float offsets:
//   U   0     (12288)  U[t*16+hq] as float4 accum (t<192, h quads)
//   Cc  12288 (192)    sum_s exp(0.125 kk[s,t])
//   mE  12480 (192)    max_s exp(0.125 kk[s,t])
//   lk  12672 (192)    log(mE)
//   mq  12864 (16)
//   Dq  12880 (16)
//   E   12896 (1056)   exp tile [32][33]
//   Qt  13952 (3264)   [192][17] qk tile -> A
//   k1s 17216 (2176)   [32][17] float4
//   k2s 19392 (2176)
//   svs 21568 (2176)
#define ZQ_SMEM_FLOATS 23744

__global__ void zq_kernel(const float* __restrict__ k1,
                          const float* __restrict__ k2,
                          const float* __restrict__ qin,
                          const float* __restrict__ v2,
                          float* __restrict__ outZ,
                          float* __restrict__ outM) {
    extern __shared__ float sm[];
    float4* U4  = reinterpret_cast<float4*>(sm);
    float*  Cc  = sm + 12288;
    float*  mE  = sm + 12480;
    float*  lk  = sm + 12672;
    float*  mq  = sm + 12864;
    float*  Dq  = sm + 12880;
    float*  E   = sm + 12896;
    float*  Qt  = sm + 13952;
    float4* k1s = reinterpret_cast<float4*>(sm + 17216);
    float4* k2s = reinterpret_cast<float4*>(sm + 19392);
    float4* svs = reinterpret_cast<float4*>(sm + 21568);

    int qt = blockIdx.x;
    int n  = blockIdx.y;
    int T = qt * 16 + 16;
    int tid = threadIdx.x;               // 256
    const float* k1h = k1 + n * S * HD;
    const float* k2h = k2 + n * S * HD;
    const float* qh  = qin + n * S * HD;
    const float* v2h = v2 + n * S * HD;
    const float* svh = g_sv1 + n * S * HD;

    // init accumulators
    for (int i = tid; i < 3072; i += 256) U4[i] = make_float4(0.f, 0.f, 0.f, 0.f);
    if (tid < 192) { Cc[tid] = 0.f; mE[tid] = 0.f; }

    int ty = tid >> 4, tx = tid & 15;

    // ---- main streaming loop over 32x32 (s,t) tiles
    for (int s0 = 0; s0 < T; s0 += 32) {
        __syncthreads();
        // stage k1 + sv1 rows s0..s0+31
#pragma unroll
        for (int k = 0; k < 2; k++) {
            int idx = tid + k * 256;
            int r = idx >> 4, c4 = idx & 15;
            k1s[r * 17 + c4] = reinterpret_cast<const float4*>(k1h + (s0 + r) * HD)[c4];
            svs[r * 17 + c4] = reinterpret_cast<const float4*>(svh + (s0 + r) * HD)[c4];
        }
        for (int t0 = s0; t0 < T; t0 += 32) {
            __syncthreads();
#pragma unroll
            for (int k = 0; k < 2; k++) {
                int idx = tid + k * 256;
                int r = idx >> 4, c4 = idx & 15;
                k2s[r * 17 + c4] = reinterpret_cast<const float4*>(k2h + (t0 + r) * HD)[c4];
            }
            __syncthreads();
            // kk 32x32 tile, 2x2 per thread
            float a00 = 0.f, a01 = 0.f, a10 = 0.f, a11 = 0.f;
#pragma unroll
            for (int k4 = 0; k4 < 16; k4++) {
                float4 p0 = k1s[ty * 17 + k4];
                float4 p1 = k1s[(ty + 16) * 17 + k4];
                float4 q0 = k2s[tx * 17 + k4];
                float4 q1 = k2s[(tx + 16) * 17 + k4];
                a00 += p0.x*q0.x + p0.y*q0.y + p0.z*q0.z + p0.w*q0.w;
                a01 += p0.x*q1.x + p0.y*q1.y + p0.z*q1.z + p0.w*q1.w;
                a10 += p1.x*q0.x + p1.y*q0.y + p1.z*q0.z + p1.w*q0.w;
                a11 += p1.x*q1.x + p1.y*q1.y + p1.z*q1.z + p1.w*q1.w;
            }
            {
                int s_a = s0 + ty, s_b = s0 + ty + 16;
                int t_a = t0 + tx, t_b = t0 + tx + 16;
                E[ty * 33 + tx]             = (s_a <= t_a && t_a < T) ? __expf(0.125f * a00) : 0.f;
                E[ty * 33 + tx + 16]        = (s_a <= t_b && t_b < T) ? __expf(0.125f * a01) : 0.f;
                E[(ty + 16) * 33 + tx]      = (s_b <= t_a && t_a < T) ? __expf(0.125f * a10) : 0.f;
                E[(ty + 16) * 33 + tx + 16] = (s_b <= t_b && t_b < T) ? __expf(0.125f * a11) : 0.f;
            }
            __syncthreads();
            // stats: Cc / mE per column t
            {
                int tl = tid >> 3, sg = tid & 7;
                float c = 0.f, m = 0.f;
#pragma unroll
                for (int i = 0; i < 4; i++) {
                    float e = E[(sg * 4 + i) * 33 + tl];
                    c += e;
                    m = fmaxf(m, e);
                }
#pragma unroll
                for (int off = 4; off > 0; off >>= 1) {
                    c += __shfl_xor_sync(0xffffffffu, c, off);
                    m = fmaxf(m, __shfl_xor_sync(0xffffffffu, m, off));
                }
                if (sg == 0) {
                    Cc[t0 + tl] += c;
                    mE[t0 + tl] = fmaxf(mE[t0 + tl], m);
                }
            }
            // U update: U[t][h] += sum_s E[s][t]*sv1[s][h]
            {
                int tl = tid >> 3, hq = tid & 7;
                float4 acc0 = U4[(t0 + tl) * 16 + hq];
                float4 acc1 = U4[(t0 + tl) * 16 + hq + 8];
#pragma unroll
                for (int s = 0; s < 32; s++) {
                    float e = E[s * 33 + tl];
                    float4 va = svs[s * 17 + hq];
                    float4 vb = svs[s * 17 + hq + 8];
                    acc0.x += e * va.x; acc0.y += e * va.y;
                    acc0.z += e * va.z; acc0.w += e * va.w;
                    acc1.x += e * vb.x; acc1.y += e * vb.y;
                    acc1.z += e * vb.z; acc1.w += e * vb.w;
                }
                U4[(t0 + tl) * 16 + hq]     = acc0;
                U4[(t0 + tl) * 16 + hq + 8] = acc1;
            }
        }
    }
    __syncthreads();

    // finalize: U *= v2 ; lk = log(mE)
    for (int idx = tid; idx < T * 16; idx += 256) {
        float4 u = U4[idx];
        float4 v = reinterpret_cast<const float4*>(v2h)[idx];
        u.x *= v.x; u.y *= v.y; u.z *= v.z; u.w *= v.w;
        U4[idx] = u;
    }
    if (tid < T) lk[tid] = __logf(mE[tid]);
    __syncthreads();

    // stage q rows (16) into k1s
    if (tid < 256) {
        int r = tid >> 4, c4 = tid & 15;
        k1s[r * 17 + c4] = reinterpret_cast<const float4*>(qh + (qt * 16 + r) * HD)[c4];
    }

    // Qt[t][ql] = k2[t] . q[qt*16+ql]
    for (int t0 = 0; t0 < T; t0 += 16) {
        __syncthreads();
        {
            int r = tid >> 4, c4 = tid & 15;
            k2s[r * 17 + c4] = reinterpret_cast<const float4*>(k2h + (t0 + r) * HD)[c4];
        }
        __syncthreads();
        float acc = 0.f;
#pragma unroll
        for (int k4 = 0; k4 < 16; k4++) {
            float4 p = k2s[ty * 17 + k4];
            float4 q = k1s[tx * 17 + k4];
            acc += p.x*q.x + p.y*q.y + p.z*q.z + p.w*q.w;
        }
        Qt[(t0 + ty) * 17 + tx] = acc;
    }
    __syncthreads();

    // mq[ql] = max_{t<=q} (0.125*qk + lk[t])
    if (tid < 16) {
        int q = qt * 16 + tid;
        float m = -INFINITY;
        for (int t = 0; t <= q; t++)
            m = fmaxf(m, 0.125f * Qt[t * 17 + tid] + lk[t]);
        mq[tid] = m;
    }
    __syncthreads();

    // A in place
    for (int idx = tid; idx < T * 16; idx += 256) {
        int t = idx >> 4, ql = idx & 15;
        int q = qt * 16 + ql;
        float v = Qt[t * 17 + ql];
        Qt[t * 17 + ql] = (t <= q) ? __expf(0.125f * v - mq[ql]) : 0.f;
    }
    __syncthreads();

    // D + M
    if (tid < 16) {
        int q = qt * 16 + tid;
        float d = 0.f;
        for (int t = 0; t <= q; t++) d += Qt[t * 17 + tid] * Cc[t];
        Dq[tid] = d;
        outM[n * S + q] = mq[tid] + logf(d + 0.01f);
    }
    __syncthreads();

    // z
    {
        int ql = tid >> 4, hq = tid & 15;
        int q = qt * 16 + ql;
        float4 acc = make_float4(0.f, 0.f, 0.f, 0.f);
        for (int t = 0; t <= q; t++) {
            float a = Qt[t * 17 + ql];
            float4 u = U4[t * 16 + hq];
            acc.x += a * u.x; acc.y += a * u.y;
            acc.z += a * u.z; acc.w += a * u.w;
        }
        float inv = 1.0f / Dq[ql];
        acc.x *= inv; acc.y *= inv; acc.z *= inv; acc.w *= inv;
        reinterpret_cast<float4*>(outZ)[(n * S + q) * 16 + hq] = acc;
    }
}

// ------- score[n][s][t][q] = mask ? -1e6 : kk[s,t]+qk[t,q]  (226 MB store) --
__global__ void score_kernel(float* __restrict__ out) {
    unsigned i = blockIdx.x * blockDim.x + threadIdx.x;
    int q4 = i % 48;
    unsigned row = i / 48;
    int t = row % S;
    unsigned r2 = row / S;
    int s = r2 % S;
    int n = r2 / S;
    float kkv = g_kk[(n * S + s) * S + t];
    float4 qv = reinterpret_cast<const float4*>(g_qk)[(n * S + t) * 48 + q4];
    int q0 = q4 * 4;
    bool rowmask = (s > t);
    float4 o;
    o.x = (rowmask || t > q0)     ? -1000000.0f : kkv + qv.x;
    o.y = (rowmask || t > q0 + 1) ? -1000000.0f : kkv + qv.y;
    o.z = (rowmask || t > q0 + 2) ? -1000000.0f : kkv + qv.z;
    o.w = (rowmask || t > q0 + 3) ? -1000000.0f : kkv + qv.w;
    reinterpret_cast<float4*>(out)[i] = o;
}

// ------- vgated[n][s][t][h] = sv1[s,h]*v2[t,h]  (75 MB store) ---------------
__global__ void vgated_kernel(float* __restrict__ out, const float* __restrict__ v2) {
    unsigned i = blockIdx.x * blockDim.x + threadIdx.x;
    int h4 = i % 16;
    unsigned row = i / 16;
    int t = row % S;
    unsigned r2 = row / S;
    int s = r2 % S;
    int n = r2 / S;
    float4 a = reinterpret_cast<const float4*>(g_sv1)[(n * S + s) * 16 + h4];
    float4 b = reinterpret_cast<const float4*>(v2)[(n * S + t) * 16 + h4];
    float4 o;
    o.x = a.x * b.x;
    o.y = a.y * b.y;
    o.z = a.z * b.z;
    o.w = a.w * b.w;
    reinterpret_cast<float4*>(out)[i] = o;
}

extern "C" void kernel_launch(void* const* d_in, const int* in_sizes, int n_in,
                              void* d_out, int out_size) {
    const float* q  = (const float*)d_in[0];
    const float* k1 = (const float*)d_in[1];
    const float* k2 = (const float*)d_in[2];
    const float* v1 = (const float*)d_in[3];
    const float* v2 = (const float*)d_in[4];
    float* out = (float*)d_out;

    cudaFuncSetAttribute(zq_kernel,
                         cudaFuncAttributeMaxDynamicSharedMemorySize,
                         ZQ_SMEM_FLOATS * sizeof(float));

    // 1. silu(v1) -> g_sv1
    silu_kernel<<<(NHEAD * S * HD + 255) / 256, 256>>>(v1);

    // 2. z + M: self-contained, 96 blocks
    {
        dim3 g(12, NHEAD);
        zq_kernel<<<g, 256, ZQ_SMEM_FLOATS * sizeof(float)>>>(
            k1, k2, q, v2, out + Z_OFF, out + M_OFF);
    }

    // 3. qk/kk scratch for score
    {
        dim3 g(6, 6, NHEAD);
        gemm_abt_kernel<<<g, 256>>>(k2, q, g_qk);
        gemm_abt_kernel<<<g, 256>>>(k1, k2, g_kk);
    }

    // 4. big broadcast writes
    score_kernel<<<(NHEAD * S * S * 48) / 256, 256>>>(out + SCORE_OFF);
    vgated_kernel<<<(NHEAD * S * S * 16) / 256, 256>>>(out + VG_OFF, v2);
}

// round 8
// speedup vs baseline: 5.2726x; 1.3034x over previous
#include <cuda_runtime.h>
#include <math.h>

#define S 192
#define HD 64
#define NHEAD 8
#define SS (S*S)

// Output layout (concatenated flattened tuple, reference return order):
#define Z_OFF      0u
#define SCORE_OFF  98304u
#define VG_OFF     56721408u
#define M_OFF      75595776u

// scratch (device globals; no allocation allowed)
__device__ float g_qk[NHEAD * SS];      // [n][t][q] (score)
__device__ float g_kk[NHEAD * SS];      // [n][s][t] (score)
__device__ float g_sv1[NHEAD * S * HD]; // silu(v1)
__device__ float g_U[NHEAD * S * HD];   // [n][t][h] = v2*sum_s E*sv1  (Z1->Z2)
__device__ float g_Cc[NHEAD * S];       // sum_s exp(0.125 kk[s,t])    (Z1->Z2)
__device__ float g_lk[NHEAD * S];       // log(max_s exp(0.125 kk))    (Z1->Z2)

// ---------------- silu(v1) --------------------------------------------------
__global__ void silu_kernel(const float* __restrict__ v1) {
    int i = blockIdx.x * blockDim.x + threadIdx.x;
    if (i < NHEAD * S * HD) {
        float x = v1[i];
        g_sv1[i] = x / (1.0f + expf(-x));
    }
}

// ------- C[n][i][j] = dot(A[n][i][:], B[n][j][:]) ; 32x32 tile, 2x2/thread --
__global__ void gemm_abt_kernel(const float* __restrict__ A,
                                const float* __restrict__ B,
                                float* __restrict__ C) {
    __shared__ float4 As4[32 * 17];
    __shared__ float4 Bs4[32 * 17];
    int n = blockIdx.z;
    int i0 = blockIdx.y * 32, j0 = blockIdx.x * 32;
    int tid = threadIdx.x;
    int ty = tid >> 4, tx = tid & 15;
    const float* Ah = A + (n * S + i0) * HD;
    const float* Bh = B + (n * S + j0) * HD;
#pragma unroll
    for (int k = 0; k < 2; k++) {
        int idx = tid + k * 256;
        int r = idx >> 4, c4 = idx & 15;
        As4[r * 17 + c4] = reinterpret_cast<const float4*>(Ah + r * HD)[c4];
        Bs4[r * 17 + c4] = reinterpret_cast<const float4*>(Bh + r * HD)[c4];
    }
    __syncthreads();
    float a00 = 0.f, a01 = 0.f, a10 = 0.f, a11 = 0.f;
#pragma unroll
    for (int k4 = 0; k4 < 16; k4++) {
        float4 p0 = As4[ty * 17 + k4];
        float4 p1 = As4[(ty + 16) * 17 + k4];
        float4 q0 = Bs4[tx * 17 + k4];
        float4 q1 = Bs4[(tx + 16) * 17 + k4];
        a00 += p0.x*q0.x + p0.y*q0.y + p0.z*q0.z + p0.w*q0.w;
        a01 += p0.x*q1.x + p0.y*q1.y + p0.z*q1.z + p0.w*q1.w;
        a10 += p1.x*q0.x + p1.y*q0.y + p1.z*q0.z + p1.w*q0.w;
        a11 += p1.x*q1.x + p1.y*q1.y + p1.z*q1.z + p1.w*q1.w;
    }
    float* Cr = C + n * SS;
    Cr[(i0 + ty) * S + j0 + tx]           = a00;
    Cr[(i0 + ty) * S + j0 + tx + 16]      = a01;
    Cr[(i0 + ty + 16) * S + j0 + tx]      = a10;
    Cr[(i0 + ty + 16) * S + j0 + tx + 16] = a11;
}

// ---------------- Z1: per (t-tile, head): E columns, Cc, lk, U tile ---------
// smem floats: svs 0 (12288) | Est 12288 (3264) | k1s 15552 (1088) | k2s 16640 (1088)
#define Z1_SMEM_FLOATS 17728

__global__ void z1_kernel(const float* __restrict__ k1,
                          const float* __restrict__ k2,
                          const float* __restrict__ v2) {
    extern __shared__ float sm[];
    float4* svs = reinterpret_cast<float4*>(sm);          // [s*16+hq]
    float*  Est = sm + 12288;                              // [s*17+tl]
    float4* k1s = reinterpret_cast<float4*>(sm + 15552);   // [16*17]
    float4* k2s = reinterpret_cast<float4*>(sm + 16640);   // [16*17]

    int tt = blockIdx.x, n = blockIdx.y;
    int t0 = tt * 16, tmax = t0 + 15, T = tmax + 1;
    int tid = threadIdx.x;
    int ty = tid >> 4, tx = tid & 15;
    const float* k1h = k1 + n * S * HD;
    const float* k2h = k2 + n * S * HD;
    const float* v2h = v2 + n * S * HD;
    const float* svh = g_sv1 + n * S * HD;

    // stage k2 t-tile + sv1 rows [0,T)
    k2s[ty * 17 + tx] = reinterpret_cast<const float4*>(k2h + (t0 + ty) * HD)[tx];
    for (int i = tid; i < T * 16; i += 256)
        svs[i] = reinterpret_cast<const float4*>(svh)[i];

    // E tile columns: loop s-blocks
    for (int s0 = 0; s0 <= t0; s0 += 16) {
        __syncthreads();
        k1s[ty * 17 + tx] = reinterpret_cast<const float4*>(k1h + (s0 + ty) * HD)[tx];
        __syncthreads();
        float acc = 0.f;
#pragma unroll
        for (int k4 = 0; k4 < 16; k4++) {
            float4 p = k1s[ty * 17 + k4];
            float4 q = k2s[tx * 17 + k4];
            acc += p.x*q.x + p.y*q.y + p.z*q.z + p.w*q.w;
        }
        int s = s0 + ty, t = t0 + tx;
        Est[s * 17 + tx] = (s <= t) ? __expf(0.125f * acc) : 0.f;
    }
    __syncthreads();

    // stats per t: Cc, lk  (16 partials per column)
    {
        int tl = tid >> 4, part = tid & 15;
        float c = 0.f, m = 0.f;
        for (int s = part; s < T; s += 16) {
            float e = Est[s * 17 + tl];
            c += e;
            m = fmaxf(m, e);
        }
#pragma unroll
        for (int off = 8; off > 0; off >>= 1) {
            c += __shfl_xor_sync(0xffffffffu, c, off);
            m = fmaxf(m, __shfl_xor_sync(0xffffffffu, m, off));
        }
        if (part == 0) {
            g_Cc[n * S + t0 + tl] = c;
            g_lk[n * S + t0 + tl] = __logf(m);
        }
    }

    // U tile: U[t0+tl][h] = v2 * sum_s Est[s][tl]*sv1[s][h]
    {
        int tl = tid >> 4, hq = tid & 15;
        float4 acc = make_float4(0.f, 0.f, 0.f, 0.f);
        for (int s = 0; s < T; s++) {
            float e = Est[s * 17 + tl];
            float4 v = svs[s * 16 + hq];
            acc.x += e * v.x; acc.y += e * v.y;
            acc.z += e * v.z; acc.w += e * v.w;
        }
        float4 vv = reinterpret_cast<const float4*>(v2h + (t0 + tl) * HD)[hq];
        acc.x *= vv.x; acc.y *= vv.y; acc.z *= vv.z; acc.w *= vv.w;
        reinterpret_cast<float4*>(g_U)[(n * S + t0 + tl) * 16 + hq] = acc;
    }
}

// ---------------- Z2: per (q-tile, head): qk, softmax, z, M ------------------
// smem floats: Us 0 (12288) | Qt 12288 (3264) | ks 15552 (1088) | qs 16640 (1088)
//              Ccs 17728 (192) | lks 17920 (192) | mq 18112 (16) | Dq 18128 (16)
#define Z2_SMEM_FLOATS 18144

__global__ void z2_kernel(const float* __restrict__ k2,
                          const float* __restrict__ qin,
                          float* __restrict__ outZ,
                          float* __restrict__ outM) {
    extern __shared__ float sm[];
    float4* Us  = reinterpret_cast<float4*>(sm);           // [t*16+hq]
    float*  Qt  = sm + 12288;                               // [t*17+ql]
    float4* ks  = reinterpret_cast<float4*>(sm + 15552);
    float4* qs  = reinterpret_cast<float4*>(sm + 16640);
    float*  Ccs = sm + 17728;
    float*  lks = sm + 17920;
    float*  mq  = sm + 18112;
    float*  Dq  = sm + 18128;

    int qt = blockIdx.x, n = blockIdx.y;
    int q0 = qt * 16, T = q0 + 16;
    int tid = threadIdx.x;
    int ty = tid >> 4, tx = tid & 15;
    const float* k2h = k2 + n * S * HD;
    const float* qh  = qin + n * S * HD;

    // stage q rows, U, Cc, lk
    qs[ty * 17 + tx] = reinterpret_cast<const float4*>(qh + (q0 + ty) * HD)[tx];
    for (int i = tid; i < T * 16; i += 256)
        Us[i] = reinterpret_cast<const float4*>(g_U)[n * S * 16 + i];
    for (int i = tid; i < T; i += 256) {
        Ccs[i] = g_Cc[n * S + i];
        lks[i] = g_lk[n * S + i];
    }

    // Qt[t][ql] = k2[t].q[q0+ql]
    for (int t0 = 0; t0 < T; t0 += 16) {
        __syncthreads();
        ks[ty * 17 + tx] = reinterpret_cast<const float4*>(k2h + (t0 + ty) * HD)[tx];
        __syncthreads();
        float acc = 0.f;
#pragma unroll
        for (int k4 = 0; k4 < 16; k4++) {
            float4 p = ks[ty * 17 + k4];
            float4 q = qs[tx * 17 + k4];
            acc += p.x*q.x + p.y*q.y + p.z*q.z + p.w*q.w;
        }
        Qt[(t0 + ty) * 17 + tx] = acc;
    }
    __syncthreads();

    // mq[ql] = max_{t<=q} (0.125 qk + lk)
    if (tid < 16) {
        int q = q0 + tid;
        float m = -INFINITY;
        for (int t = 0; t <= q; t++)
            m = fmaxf(m, 0.125f * Qt[t * 17 + tid] + lks[t]);
        mq[tid] = m;
    }
    __syncthreads();

    // A in place
    for (int idx = tid; idx < T * 16; idx += 256) {
        int t = idx >> 4, ql = idx & 15;
        int q = q0 + ql;
        float v = Qt[t * 17 + ql];
        Qt[t * 17 + ql] = (t <= q) ? __expf(0.125f * v - mq[ql]) : 0.f;
    }
    __syncthreads();

    // D + M
    if (tid < 16) {
        int q = q0 + tid;
        float d = 0.f;
        for (int t = 0; t <= q; t++) d += Qt[t * 17 + tid] * Ccs[t];
        Dq[tid] = d;
        outM[n * S + q] = mq[tid] + logf(d + 0.01f);
    }
    __syncthreads();

    // z
    {
        int ql = ty, hq = tx;
        int q = q0 + ql;
        float4 acc = make_float4(0.f, 0.f, 0.f, 0.f);
        for (int t = 0; t <= q; t++) {
            float a = Qt[t * 17 + ql];
            float4 u = Us[t * 16 + hq];
            acc.x += a * u.x; acc.y += a * u.y;
            acc.z += a * u.z; acc.w += a * u.w;
        }
        float inv = 1.0f / Dq[ql];
        acc.x *= inv; acc.y *= inv; acc.z *= inv; acc.w *= inv;
        reinterpret_cast<float4*>(outZ)[(n * S + q) * 16 + hq] = acc;
    }
}

// ------- score[n][s][t][q] = mask ? -1e6 : kk[s,t]+qk[t,q]  (226 MB store) --
__global__ void score_kernel(float* __restrict__ out) {
    unsigned i = blockIdx.x * blockDim.x + threadIdx.x;
    int q4 = i % 48;
    unsigned row = i / 48;
    int t = row % S;
    unsigned r2 = row / S;
    int s = r2 % S;
    int n = r2 / S;
    float kkv = g_kk[(n * S + s) * S + t];
    float4 qv = reinterpret_cast<const float4*>(g_qk)[(n * S + t) * 48 + q4];
    int q0 = q4 * 4;
    bool rowmask = (s > t);
    float4 o;
    o.x = (rowmask || t > q0)     ? -1000000.0f : kkv + qv.x;
    o.y = (rowmask || t > q0 + 1) ? -1000000.0f : kkv + qv.y;
    o.z = (rowmask || t > q0 + 2) ? -1000000.0f : kkv + qv.z;
    o.w = (rowmask || t > q0 + 3) ? -1000000.0f : kkv + qv.w;
    reinterpret_cast<float4*>(out)[i] = o;
}

// ------- vgated[n][s][t][h] = sv1[s,h]*v2[t,h]  (75 MB store) ---------------
__global__ void vgated_kernel(float* __restrict__ out, const float* __restrict__ v2) {
    unsigned i = blockIdx.x * blockDim.x + threadIdx.x;
    int h4 = i % 16;
    unsigned row = i / 16;
    int t = row % S;
    unsigned r2 = row / S;
    int s = r2 % S;
    int n = r2 / S;
    float4 a = reinterpret_cast<const float4*>(g_sv1)[(n * S + s) * 16 + h4];
    float4 b = reinterpret_cast<const float4*>(v2)[(n * S + t) * 16 + h4];
    float4 o;
    o.x = a.x * b.x;
    o.y = a.y * b.y;
    o.z = a.z * b.z;
    o.w = a.w * b.w;
    reinterpret_cast<float4*>(out)[i] = o;
}

extern "C" void kernel_launch(void* const* d_in, const int* in_sizes, int n_in,
                              void* d_out, int out_size) {
    const float* q  = (const float*)d_in[0];
    const float* k1 = (const float*)d_in[1];
    const float* k2 = (const float*)d_in[2];
    const float* v1 = (const float*)d_in[3];
    const float* v2 = (const float*)d_in[4];
    float* out = (float*)d_out;

    cudaFuncSetAttribute(z1_kernel, cudaFuncAttributeMaxDynamicSharedMemorySize,
                         Z1_SMEM_FLOATS * sizeof(float));
    cudaFuncSetAttribute(z2_kernel, cudaFuncAttributeMaxDynamicSharedMemorySize,
                         Z2_SMEM_FLOATS * sizeof(float));

    // 1. silu(v1) -> g_sv1
    silu_kernel<<<(NHEAD * S * HD + 255) / 256, 256>>>(v1);

    // 2. qk/kk scratch for score
    {
        dim3 g(6, 6, NHEAD);
        gemm_abt_kernel<<<g, 256>>>(k2, q, g_qk);
        gemm_abt_kernel<<<g, 256>>>(k1, k2, g_kk);
    }

    // 3. z path: Z1 (U/Cc/lk per t-tile) then Z2 (softmax + z per q-tile)
    {
        dim3 g(12, NHEAD);
        z1_kernel<<<g, 256, Z1_SMEM_FLOATS * sizeof(float)>>>(k1, k2, v2);
        z2_kernel<<<g, 256, Z2_SMEM_FLOATS * sizeof(float)>>>(
            k2, q, out + Z_OFF, out + M_OFF);
    }

    // 4. big broadcast writes
    score_kernel<<<(NHEAD * S * S * 48) / 256, 256>>>(out + SCORE_OFF);
    vgated_kernel<<<(NHEAD * S * S * 16) / 256, 256>>>(out + VG_OFF, v2);
}

// round 9
// speedup vs baseline: 6.8404x; 1.2973x over previous
#include <cuda_runtime.h>
#include <math.h>

#define S 192
#define HD 64
#define NHEAD 8
#define SS (S*S)

// Output layout (concatenated flattened tuple, reference return order):
#define Z_OFF      0u
#define SCORE_OFF  98304u
#define VG_OFF     56721408u
#define M_OFF      75595776u

// scratch (device globals; no allocation allowed)
__device__ float g_qk[NHEAD * SS];      // [n][t][q] (A.gemm -> B.score)
__device__ float g_kk[NHEAD * SS];      // [n][s][t] (A.gemm -> B.score)
__device__ float g_sv1[NHEAD * S * HD]; // silu(v1)  (A.silu -> B.vgated)
__device__ float g_U[NHEAD * S * HD];   // (A.z1 -> B.z2)
__device__ float g_Cc[NHEAD * S];       // (A.z1 -> B.z2)
__device__ float g_lk[NHEAD * S];       // (A.z1 -> B.z2)

// ============================ MEGA KERNEL A =================================
// blocks: [0,96)   z1 role   (tt = b%12, n = b/12), silu inline
//         [96,384) gemm g_qk (k2 . q^T)
//         [384,672) gemm g_kk (k1 . k2^T)
//         [672,684) silu writer -> g_sv1
// smem: 17728 floats (z1 role usage; others use a subset)
#define A_SMEM_FLOATS 17728

__global__ __launch_bounds__(256) void megaA(
    const float* __restrict__ qin, const float* __restrict__ k1,
    const float* __restrict__ k2, const float* __restrict__ v1,
    const float* __restrict__ v2) {
    extern __shared__ float sm[];
    int b = blockIdx.x;
    int tid = threadIdx.x;
    int ty = tid >> 4, tx = tid & 15;

    if (b < 96) {
        // ---------------- z1 role ----------------
        float4* svs = reinterpret_cast<float4*>(sm);          // [s*16+hq], 3072 f4
        float*  Est = sm + 12288;                              // [s*17+tl], 3264
        float4* k1s = reinterpret_cast<float4*>(sm + 15552);   // 272 f4
        float4* k2s = reinterpret_cast<float4*>(sm + 16640);   // 272 f4
        int tt = b % 12, n = b / 12;
        int t0 = tt * 16, T = t0 + 16;
        const float* k1h = k1 + n * S * HD;
        const float* k2h = k2 + n * S * HD;
        const float* v1h = v1 + n * S * HD;
        const float* v2h = v2 + n * S * HD;

        k2s[ty * 17 + tx] = reinterpret_cast<const float4*>(k2h + (t0 + ty) * HD)[tx];
        for (int i = tid; i < T * 16; i += 256) {
            float4 x = reinterpret_cast<const float4*>(v1h)[i];
            x.x = x.x / (1.f + __expf(-x.x));
            x.y = x.y / (1.f + __expf(-x.y));
            x.z = x.z / (1.f + __expf(-x.z));
            x.w = x.w / (1.f + __expf(-x.w));
            svs[i] = x;
        }
        for (int s0 = 0; s0 <= t0; s0 += 16) {
            __syncthreads();
            k1s[ty * 17 + tx] = reinterpret_cast<const float4*>(k1h + (s0 + ty) * HD)[tx];
            __syncthreads();
            float c0 = 0.f, c1 = 0.f, c2 = 0.f, c3 = 0.f;
#pragma unroll
            for (int k4 = 0; k4 < 16; k4++) {
                float4 p = k1s[ty * 17 + k4];
                float4 r = k2s[tx * 17 + k4];
                c0 += p.x * r.x; c1 += p.y * r.y;
                c2 += p.z * r.z; c3 += p.w * r.w;
            }
            float acc = (c0 + c1) + (c2 + c3);
            int s_ = s0 + ty, t_ = t0 + tx;
            Est[s_ * 17 + tx] = (s_ <= t_) ? __expf(0.125f * acc) : 0.f;
        }
        __syncthreads();
        // stats: Cc, lk
        {
            float c = 0.f, m = 0.f;
            for (int s_ = tx; s_ < T; s_ += 16) {
                float e = Est[s_ * 17 + ty];
                c += e;
                m = fmaxf(m, e);
            }
#pragma unroll
            for (int off = 8; off; off >>= 1) {
                c += __shfl_xor_sync(0xffffffffu, c, off);
                m = fmaxf(m, __shfl_xor_sync(0xffffffffu, m, off));
            }
            if (tx == 0) {
                g_Cc[n * S + t0 + ty] = c;
                g_lk[n * S + t0 + ty] = __logf(m);
            }
        }
        // U tile: 4 independent chains, unroll 4
        {
            int tl = ty, hq = tx;
            float4 a0 = make_float4(0,0,0,0), a1 = a0, a2 = a0, a3 = a0;
            for (int s_ = 0; s_ < T; s_ += 4) {
                float e0 = Est[s_ * 17 + tl];
                float e1 = Est[(s_ + 1) * 17 + tl];
                float e2 = Est[(s_ + 2) * 17 + tl];
                float e3 = Est[(s_ + 3) * 17 + tl];
                float4 u0 = svs[s_ * 16 + hq];
                float4 u1 = svs[(s_ + 1) * 16 + hq];
                float4 u2 = svs[(s_ + 2) * 16 + hq];
                float4 u3 = svs[(s_ + 3) * 16 + hq];
                a0.x += e0 * u0.x; a0.y += e0 * u0.y; a0.z += e0 * u0.z; a0.w += e0 * u0.w;
                a1.x += e1 * u1.x; a1.y += e1 * u1.y; a1.z += e1 * u1.z; a1.w += e1 * u1.w;
                a2.x += e2 * u2.x; a2.y += e2 * u2.y; a2.z += e2 * u2.z; a2.w += e2 * u2.w;
                a3.x += e3 * u3.x; a3.y += e3 * u3.y; a3.z += e3 * u3.z; a3.w += e3 * u3.w;
            }
            float4 acc;
            acc.x = (a0.x + a1.x) + (a2.x + a3.x);
            acc.y = (a0.y + a1.y) + (a2.y + a3.y);
            acc.z = (a0.z + a1.z) + (a2.z + a3.z);
            acc.w = (a0.w + a1.w) + (a2.w + a3.w);
            float4 vv = reinterpret_cast<const float4*>(v2h + (t0 + tl) * HD)[hq];
            acc.x *= vv.x; acc.y *= vv.y; acc.z *= vv.z; acc.w *= vv.w;
            reinterpret_cast<float4*>(g_U)[(n * S + t0 + tl) * 16 + hq] = acc;
        }
    } else if (b < 672) {
        // ---------------- gemm role: C[i][j] = A[i].B[j] ----------------
        float4* As4 = reinterpret_cast<float4*>(sm);          // 544 f4
        float4* Bs4 = reinterpret_cast<float4*>(sm) + 544;    // 544 f4
        int idx = b - 96;
        const float *Ain, *Bin;
        float* Cout;
        if (idx < 288) { Ain = k2; Bin = qin; Cout = g_qk; }
        else { idx -= 288; Ain = k1; Bin = k2; Cout = g_kk; }
        int j0 = (idx % 6) * 32, i0 = ((idx / 6) % 6) * 32, n = idx / 36;
        const float* Ah = Ain + (n * S + i0) * HD;
        const float* Bh = Bin + (n * S + j0) * HD;
#pragma unroll
        for (int k = 0; k < 2; k++) {
            int l = tid + k * 256;
            int r = l >> 4, c4 = l & 15;
            As4[r * 17 + c4] = reinterpret_cast<const float4*>(Ah + r * HD)[c4];
            Bs4[r * 17 + c4] = reinterpret_cast<const float4*>(Bh + r * HD)[c4];
        }
        __syncthreads();
        float a00 = 0.f, a01 = 0.f, a10 = 0.f, a11 = 0.f;
#pragma unroll
        for (int k4 = 0; k4 < 16; k4++) {
            float4 p0 = As4[ty * 17 + k4];
            float4 p1 = As4[(ty + 16) * 17 + k4];
            float4 r0 = Bs4[tx * 17 + k4];
            float4 r1 = Bs4[(tx + 16) * 17 + k4];
            a00 += p0.x*r0.x + p0.y*r0.y + p0.z*r0.z + p0.w*r0.w;
            a01 += p0.x*r1.x + p0.y*r1.y + p0.z*r1.z + p0.w*r1.w;
            a10 += p1.x*r0.x + p1.y*r0.y + p1.z*r0.z + p1.w*r0.w;
            a11 += p1.x*r1.x + p1.y*r1.y + p1.z*r1.z + p1.w*r1.w;
        }
        float* Cr = Cout + n * SS;
        Cr[(i0 + ty) * S + j0 + tx]           = a00;
        Cr[(i0 + ty) * S + j0 + tx + 16]      = a01;
        Cr[(i0 + ty + 16) * S + j0 + tx]      = a10;
        Cr[(i0 + ty + 16) * S + j0 + tx + 16] = a11;
    } else {
        // ---------------- silu writer -> g_sv1 ----------------
        for (int i = (b - 672) * 256 + tid; i < NHEAD * S * HD / 4; i += 12 * 256) {
            float4 x = reinterpret_cast<const float4*>(v1)[i];
            x.x = x.x / (1.f + expf(-x.x));
            x.y = x.y / (1.f + expf(-x.y));
            x.z = x.z / (1.f + expf(-x.z));
            x.w = x.w / (1.f + expf(-x.w));
            reinterpret_cast<float4*>(g_sv1)[i] = x;
        }
    }
}

// ============================ MEGA KERNEL B =================================
// blocks: [0,96)          z2 role (qt = b%12, n = b/12)
//         [96,96+55296)   score writer
//         [.., +18432)    vgated writer
// smem: 5856 floats (z2 role)
#define B_SMEM_FLOATS 5856
#define SCORE_BLOCKS 55296
#define VG_BLOCKS 18432

__global__ __launch_bounds__(256) void megaB(
    const float* __restrict__ k2, const float* __restrict__ qin,
    const float* __restrict__ v2, float* __restrict__ out) {
    extern __shared__ float sm[];
    int b = blockIdx.x;
    int tid = threadIdx.x;

    if (b < 96) {
        // ---------------- z2 role ----------------
        float*  Qt  = sm;                                     // [t*17+ql] 3264
        float4* ks  = reinterpret_cast<float4*>(sm + 3264);   // 272 f4
        float4* qs  = reinterpret_cast<float4*>(sm + 4352);   // 272 f4
        float*  Ccs = sm + 5440;
        float*  lks = sm + 5632;
        float*  mqs = sm + 5824;  // 16
        float*  Dqs = sm + 5840;  // 16
        int qt = b % 12, n = b / 12;
        int q0 = qt * 16, T = q0 + 16;
        int ty = tid >> 4, tx = tid & 15;

        qs[ty * 17 + tx] = reinterpret_cast<const float4*>(qin + (n * S + q0 + ty) * HD)[tx];
        for (int i = tid; i < T; i += 256) {
            Ccs[i] = g_Cc[n * S + i];
            lks[i] = g_lk[n * S + i];
        }
        for (int t0 = 0; t0 < T; t0 += 16) {
            __syncthreads();
            ks[ty * 17 + tx] = reinterpret_cast<const float4*>(k2 + (n * S + t0 + ty) * HD)[tx];
            __syncthreads();
            float c0 = 0.f, c1 = 0.f, c2 = 0.f, c3 = 0.f;
#pragma unroll
            for (int k4 = 0; k4 < 16; k4++) {
                float4 p = ks[ty * 17 + k4];
                float4 r = qs[tx * 17 + k4];
                c0 += p.x * r.x; c1 += p.y * r.y;
                c2 += p.z * r.z; c3 += p.w * r.w;
            }
            Qt[(t0 + ty) * 17 + tx] = (c0 + c1) + (c2 + c3);
        }
        __syncthreads();
        // mq
        {
            int ql = ty, part = tx;
            int q = q0 + ql;
            float m = -INFINITY;
            for (int t = part; t < T; t += 16)
                if (t <= q) m = fmaxf(m, 0.125f * Qt[t * 17 + ql] + lks[t]);
#pragma unroll
            for (int off = 8; off; off >>= 1)
                m = fmaxf(m, __shfl_xor_sync(0xffffffffu, m, off));
            if (part == 0) mqs[ql] = m;
        }
        __syncthreads();
        // A in place (zero beyond causal bound)
        for (int i2 = tid; i2 < T * 16; i2 += 256) {
            int t = i2 >> 4, ql = i2 & 15;
            float v = Qt[t * 17 + ql];
            Qt[t * 17 + ql] = (t <= q0 + ql) ? __expf(0.125f * v - mqs[ql]) : 0.f;
        }
        __syncthreads();
        // D + M
        {
            int ql = ty, part = tx;
            float d = 0.f;
            for (int t = part; t < T; t += 16) d += Qt[t * 17 + ql] * Ccs[t];
#pragma unroll
            for (int off = 8; off; off >>= 1)
                d += __shfl_xor_sync(0xffffffffu, d, off);
            if (part == 0) {
                Dqs[ql] = d;
                out[M_OFF + n * S + q0 + ql] = mqs[ql] + logf(d + 0.01f);
            }
        }
        __syncthreads();
        // z: U from gmem (L2-hot), 4 chains unroll 4
        {
            int ql = ty, hq = tx;
            const float4* Ug = reinterpret_cast<const float4*>(g_U) + (n * S) * 16 + hq;
            float4 a0 = make_float4(0,0,0,0), a1 = a0, a2 = a0, a3 = a0;
            for (int t = 0; t < T; t += 4) {
                float w0 = Qt[t * 17 + ql];
                float w1 = Qt[(t + 1) * 17 + ql];
                float w2 = Qt[(t + 2) * 17 + ql];
                float w3 = Qt[(t + 3) * 17 + ql];
                float4 u0 = Ug[t * 16];
                float4 u1 = Ug[(t + 1) * 16];
                float4 u2 = Ug[(t + 2) * 16];
                float4 u3 = Ug[(t + 3) * 16];
                a0.x += w0 * u0.x; a0.y += w0 * u0.y; a0.z += w0 * u0.z; a0.w += w0 * u0.w;
                a1.x += w1 * u1.x; a1.y += w1 * u1.y; a1.z += w1 * u1.z; a1.w += w1 * u1.w;
                a2.x += w2 * u2.x; a2.y += w2 * u2.y; a2.z += w2 * u2.z; a2.w += w2 * u2.w;
                a3.x += w3 * u3.x; a3.y += w3 * u3.y; a3.z += w3 * u3.z; a3.w += w3 * u3.w;
            }
            float inv = 1.0f / Dqs[ql];
            float4 acc;
            acc.x = ((a0.x + a1.x) + (a2.x + a3.x)) * inv;
            acc.y = ((a0.y + a1.y) + (a2.y + a3.y)) * inv;
            acc.z = ((a0.z + a1.z) + (a2.z + a3.z)) * inv;
            acc.w = ((a0.w + a1.w) + (a2.w + a3.w)) * inv;
            reinterpret_cast<float4*>(out + Z_OFF)[(n * S + q0 + ql) * 16 + hq] = acc;
        }
    } else if (b < 96 + SCORE_BLOCKS) {
        // ---------------- score writer ----------------
        unsigned i = (unsigned)(b - 96) * 256u + tid;
        int q4 = i % 48;
        unsigned row = i / 48;
        int t = row % S;
        unsigned r2 = row / S;
        int s = r2 % S;
        int n = r2 / S;
        float kkv = g_kk[(n * S + s) * S + t];
        float4 qv = reinterpret_cast<const float4*>(g_qk)[(n * S + t) * 48 + q4];
        int q0 = q4 * 4;
        bool rowmask = (s > t);
        float4 o;
        o.x = (rowmask || t > q0)     ? -1000000.0f : kkv + qv.x;
        o.y = (rowmask || t > q0 + 1) ? -1000000.0f : kkv + qv.y;
        o.z = (rowmask || t > q0 + 2) ? -1000000.0f : kkv + qv.z;
        o.w = (rowmask || t > q0 + 3) ? -1000000.0f : kkv + qv.w;
        reinterpret_cast<float4*>(out + SCORE_OFF)[i] = o;
    } else {
        // ---------------- vgated writer ----------------
        unsigned i = (unsigned)(b - 96 - SCORE_BLOCKS) * 256u + tid;
        int h4 = i % 16;
        unsigned row = i / 16;
        int t = row % S;
        unsigned r2 = row / S;
        int s = r2 % S;
        int n = r2 / S;
        float4 a = reinterpret_cast<const float4*>(g_sv1)[(n * S + s) * 16 + h4];
        float4 v = reinterpret_cast<const float4*>(v2)[(n * S + t) * 16 + h4];
        float4 o;
        o.x = a.x * v.x;
        o.y = a.y * v.y;
        o.z = a.z * v.z;
        o.w = a.w * v.w;
        reinterpret_cast<float4*>(out + VG_OFF)[i] = o;
    }
}

extern "C" void kernel_launch(void* const* d_in, const int* in_sizes, int n_in,
                              void* d_out, int out_size) {
    const float* q  = (const float*)d_in[0];
    const float* k1 = (const float*)d_in[1];
    const float* k2 = (const float*)d_in[2];
    const float* v1 = (const float*)d_in[3];
    const float* v2 = (const float*)d_in[4];
    float* out = (float*)d_out;

    cudaFuncSetAttribute(megaA, cudaFuncAttributeMaxDynamicSharedMemorySize,
                         A_SMEM_FLOATS * sizeof(float));
    cudaFuncSetAttribute(megaB, cudaFuncAttributeMaxDynamicSharedMemorySize,
                         B_SMEM_FLOATS * sizeof(float));

    // A: z1 (inline silu) + both gemms + silu writer  (all independent)
    megaA<<<684, 256, A_SMEM_FLOATS * sizeof(float)>>>(q, k1, k2, v1, v2);

    // B: z2 + score + vgated  (depend only on A outputs)
    megaB<<<96 + SCORE_BLOCKS + VG_BLOCKS, 256, B_SMEM_FLOATS * sizeof(float)>>>(
        k2, q, v2, out);
}

// round 10
// speedup vs baseline: 6.8556x; 1.0022x over previous
#include <cuda_runtime.h>
#include <math.h>

#define S 192
#define HD 64
#define NHEAD 8
#define SS (S*S)

// Output layout (concatenated flattened tuple, reference return order):
#define Z_OFF      0u
#define SCORE_OFF  98304u
#define VG_OFF     56721408u
#define M_OFF      75595776u

// scratch (device globals; no allocation allowed)
__device__ float g_qk[NHEAD * SS];      // [n][t][q] (A.gemm -> B.score)
__device__ float g_kk[NHEAD * SS];      // [n][s][t] (A.gemm -> B.score)
__device__ float g_sv1[NHEAD * S * HD]; // silu(v1)  (A.silu -> B.vgated)
__device__ float g_U[NHEAD * S * HD];   // (A.z1 -> B.z2)
__device__ float g_Cc[NHEAD * S];       // (A.z1 -> B.z2)
__device__ float g_lk[NHEAD * S];       // (A.z1 -> B.z2)

// ============================ MEGA KERNEL A =================================
// blocks: [0,96)   z1 role   (tt = b%12, n = b/12), silu inline
//         [96,384) gemm g_qk (k2 . q^T)
//         [384,672) gemm g_kk (k1 . k2^T)
//         [672,684) silu writer -> g_sv1
#define A_SMEM_FLOATS 17728

__global__ __launch_bounds__(256) void megaA(
    const float* __restrict__ qin, const float* __restrict__ k1,
    const float* __restrict__ k2, const float* __restrict__ v1,
    const float* __restrict__ v2) {
    extern __shared__ float sm[];
    int b = blockIdx.x;
    int tid = threadIdx.x;
    int ty = tid >> 4, tx = tid & 15;

    if (b < 96) {
        // ---------------- z1 role ----------------
        float4* svs = reinterpret_cast<float4*>(sm);          // [s*16+hq], 3072 f4
        float*  Est = sm + 12288;                              // [s*17+tl], 3264
        float4* k1s = reinterpret_cast<float4*>(sm + 15552);   // 272 f4
        float4* k2s = reinterpret_cast<float4*>(sm + 16640);   // 272 f4
        int tt = b % 12, n = b / 12;
        int t0 = tt * 16, T = t0 + 16;
        const float* k1h = k1 + n * S * HD;
        const float* k2h = k2 + n * S * HD;
        const float* v1h = v1 + n * S * HD;
        const float* v2h = v2 + n * S * HD;

        k2s[ty * 17 + tx] = reinterpret_cast<const float4*>(k2h + (t0 + ty) * HD)[tx];
        for (int i = tid; i < T * 16; i += 256) {
            float4 x = reinterpret_cast<const float4*>(v1h)[i];
            x.x = x.x / (1.f + __expf(-x.x));
            x.y = x.y / (1.f + __expf(-x.y));
            x.z = x.z / (1.f + __expf(-x.z));
            x.w = x.w / (1.f + __expf(-x.w));
            svs[i] = x;
        }
        for (int s0 = 0; s0 <= t0; s0 += 16) {
            __syncthreads();
            k1s[ty * 17 + tx] = reinterpret_cast<const float4*>(k1h + (s0 + ty) * HD)[tx];
            __syncthreads();
            float c0 = 0.f, c1 = 0.f, c2 = 0.f, c3 = 0.f;
#pragma unroll
            for (int k4 = 0; k4 < 16; k4++) {
                float4 p = k1s[ty * 17 + k4];
                float4 r = k2s[tx * 17 + k4];
                c0 += p.x * r.x; c1 += p.y * r.y;
                c2 += p.z * r.z; c3 += p.w * r.w;
            }
            float acc = (c0 + c1) + (c2 + c3);
            int s_ = s0 + ty, t_ = t0 + tx;
            Est[s_ * 17 + tx] = (s_ <= t_) ? __expf(0.125f * acc) : 0.f;
        }
        __syncthreads();
        // stats: Cc, lk
        {
            float c = 0.f, m = 0.f;
            for (int s_ = tx; s_ < T; s_ += 16) {
                float e = Est[s_ * 17 + ty];
                c += e;
                m = fmaxf(m, e);
            }
#pragma unroll
            for (int off = 8; off; off >>= 1) {
                c += __shfl_xor_sync(0xffffffffu, c, off);
                m = fmaxf(m, __shfl_xor_sync(0xffffffffu, m, off));
            }
            if (tx == 0) {
                g_Cc[n * S + t0 + ty] = c;
                g_lk[n * S + t0 + ty] = __logf(m);
            }
        }
        // U tile: 4 independent chains, unroll 4
        {
            int tl = ty, hq = tx;
            float4 a0 = make_float4(0,0,0,0), a1 = a0, a2 = a0, a3 = a0;
            for (int s_ = 0; s_ < T; s_ += 4) {
                float e0 = Est[s_ * 17 + tl];
                float e1 = Est[(s_ + 1) * 17 + tl];
                float e2 = Est[(s_ + 2) * 17 + tl];
                float e3 = Est[(s_ + 3) * 17 + tl];
                float4 u0 = svs[s_ * 16 + hq];
                float4 u1 = svs[(s_ + 1) * 16 + hq];
                float4 u2 = svs[(s_ + 2) * 16 + hq];
                float4 u3 = svs[(s_ + 3) * 16 + hq];
                a0.x += e0 * u0.x; a0.y += e0 * u0.y; a0.z += e0 * u0.z; a0.w += e0 * u0.w;
                a1.x += e1 * u1.x; a1.y += e1 * u1.y; a1.z += e1 * u1.z; a1.w += e1 * u1.w;
                a2.x += e2 * u2.x; a2.y += e2 * u2.y; a2.z += e2 * u2.z; a2.w += e2 * u2.w;
                a3.x += e3 * u3.x; a3.y += e3 * u3.y; a3.z += e3 * u3.z; a3.w += e3 * u3.w;
            }
            float4 acc;
            acc.x = (a0.x + a1.x) + (a2.x + a3.x);
            acc.y = (a0.y + a1.y) + (a2.y + a3.y);
            acc.z = (a0.z + a1.z) + (a2.z + a3.z);
            acc.w = (a0.w + a1.w) + (a2.w + a3.w);
            float4 vv = reinterpret_cast<const float4*>(v2h + (t0 + tl) * HD)[hq];
            acc.x *= vv.x; acc.y *= vv.y; acc.z *= vv.z; acc.w *= vv.w;
            reinterpret_cast<float4*>(g_U)[(n * S + t0 + tl) * 16 + hq] = acc;
        }
    } else if (b < 672) {
        // ---------------- gemm role: C[i][j] = A[i].B[j] ----------------
        float4* As4 = reinterpret_cast<float4*>(sm);          // 544 f4
        float4* Bs4 = reinterpret_cast<float4*>(sm) + 544;    // 544 f4
        int idx = b - 96;
        const float *Ain, *Bin;
        float* Cout;
        if (idx < 288) { Ain = k2; Bin = qin; Cout = g_qk; }
        else { idx -= 288; Ain = k1; Bin = k2; Cout = g_kk; }
        int j0 = (idx % 6) * 32, i0 = ((idx / 6) % 6) * 32, n = idx / 36;
        const float* Ah = Ain + (n * S + i0) * HD;
        const float* Bh = Bin + (n * S + j0) * HD;
#pragma unroll
        for (int k = 0; k < 2; k++) {
            int l = tid + k * 256;
            int r = l >> 4, c4 = l & 15;
            As4[r * 17 + c4] = reinterpret_cast<const float4*>(Ah + r * HD)[c4];
            Bs4[r * 17 + c4] = reinterpret_cast<const float4*>(Bh + r * HD)[c4];
        }
        __syncthreads();
        float a00 = 0.f, a01 = 0.f, a10 = 0.f, a11 = 0.f;
#pragma unroll
        for (int k4 = 0; k4 < 16; k4++) {
            float4 p0 = As4[ty * 17 + k4];
            float4 p1 = As4[(ty + 16) * 17 + k4];
            float4 r0 = Bs4[tx * 17 + k4];
            float4 r1 = Bs4[(tx + 16) * 17 + k4];
            a00 += p0.x*r0.x + p0.y*r0.y + p0.z*r0.z + p0.w*r0.w;
            a01 += p0.x*r1.x + p0.y*r1.y + p0.z*r1.z + p0.w*r1.w;
            a10 += p1.x*r0.x + p1.y*r0.y + p1.z*r0.z + p1.w*r0.w;
            a11 += p1.x*r1.x + p1.y*r1.y + p1.z*r1.z + p1.w*r1.w;
        }
        float* Cr = Cout + n * SS;
        Cr[(i0 + ty) * S + j0 + tx]           = a00;
        Cr[(i0 + ty) * S + j0 + tx + 16]      = a01;
        Cr[(i0 + ty + 16) * S + j0 + tx]      = a10;
        Cr[(i0 + ty + 16) * S + j0 + tx + 16] = a11;
    } else {
        // ---------------- silu writer -> g_sv1 ----------------
        for (int i = (b - 672) * 256 + tid; i < NHEAD * S * HD / 4; i += 12 * 256) {
            float4 x = reinterpret_cast<const float4*>(v1)[i];
            x.x = x.x / (1.f + expf(-x.x));
            x.y = x.y / (1.f + expf(-x.y));
            x.z = x.z / (1.f + expf(-x.z));
            x.w = x.w / (1.f + expf(-x.w));
            reinterpret_cast<float4*>(g_sv1)[i] = x;
        }
    }
}

// ============================ MEGA KERNEL B =================================
// blocks: [0,96)            z2 role (qt = b%12, n = b/12)
//         [96, 96+1152)     vgated tile writer (n, s-chunk16, t-chunk16)
//         [1248, 1248+18432) score row writer (n, t, s-chunk16)
#define B_SMEM_FLOATS 5856
#define VG_BLOCKS   1152    // 8 * 12 * 12
#define SCORE_BLOCKS 18432  // 8 * 12 * 192

__global__ __launch_bounds__(256) void megaB(
    const float* __restrict__ k2, const float* __restrict__ qin,
    const float* __restrict__ v2, float* __restrict__ out) {
    extern __shared__ float sm[];
    int b = blockIdx.x;
    int tid = threadIdx.x;

    if (b < 96) {
        // ---------------- z2 role ----------------
        float*  Qt  = sm;                                     // [t*17+ql] 3264
        float4* ks  = reinterpret_cast<float4*>(sm + 3264);   // 272 f4
        float4* qs  = reinterpret_cast<float4*>(sm + 4352);   // 272 f4
        float*  Ccs = sm + 5440;
        float*  lks = sm + 5632;
        float*  mqs = sm + 5824;  // 16
        float*  Dqs = sm + 5840;  // 16
        int qt = b % 12, n = b / 12;
        int q0 = qt * 16, T = q0 + 16;
        int ty = tid >> 4, tx = tid & 15;

        qs[ty * 17 + tx] = reinterpret_cast<const float4*>(qin + (n * S + q0 + ty) * HD)[tx];
        for (int i = tid; i < T; i += 256) {
            Ccs[i] = g_Cc[n * S + i];
            lks[i] = g_lk[n * S + i];
        }
        for (int t0 = 0; t0 < T; t0 += 16) {
            __syncthreads();
            ks[ty * 17 + tx] = reinterpret_cast<const float4*>(k2 + (n * S + t0 + ty) * HD)[tx];
            __syncthreads();
            float c0 = 0.f, c1 = 0.f, c2 = 0.f, c3 = 0.f;
#pragma unroll
            for (int k4 = 0; k4 < 16; k4++) {
                float4 p = ks[ty * 17 + k4];
                float4 r = qs[tx * 17 + k4];
                c0 += p.x * r.x; c1 += p.y * r.y;
                c2 += p.z * r.z; c3 += p.w * r.w;
            }
            Qt[(t0 + ty) * 17 + tx] = (c0 + c1) + (c2 + c3);
        }
        __syncthreads();
        // mq
        {
            int ql = ty, part = tx;
            int q = q0 + ql;
            float m = -INFINITY;
            for (int t = part; t < T; t += 16)
                if (t <= q) m = fmaxf(m, 0.125f * Qt[t * 17 + ql] + lks[t]);
#pragma unroll
            for (int off = 8; off; off >>= 1)
                m = fmaxf(m, __shfl_xor_sync(0xffffffffu, m, off));
            if (part == 0) mqs[ql] = m;
        }
        __syncthreads();
        // A in place
        for (int i2 = tid; i2 < T * 16; i2 += 256) {
            int t = i2 >> 4, ql = i2 & 15;
            float v = Qt[t * 17 + ql];
            Qt[t * 17 + ql] = (t <= q0 + ql) ? __expf(0.125f * v - mqs[ql]) : 0.f;
        }
        __syncthreads();
        // D + M
        {
            int ql = ty, part = tx;
            float d = 0.f;
            for (int t = part; t < T; t += 16) d += Qt[t * 17 + ql] * Ccs[t];
#pragma unroll
            for (int off = 8; off; off >>= 1)
                d += __shfl_xor_sync(0xffffffffu, d, off);
            if (part == 0) {
                Dqs[ql] = d;
                out[M_OFF + n * S + q0 + ql] = mqs[ql] + logf(d + 0.01f);
            }
        }
        __syncthreads();
        // z: U from gmem (L2-hot), 4 chains unroll 4
        {
            int ql = ty, hq = tx;
            const float4* Ug = reinterpret_cast<const float4*>(g_U) + (n * S) * 16 + hq;
            float4 a0 = make_float4(0,0,0,0), a1 = a0, a2 = a0, a3 = a0;
            for (int t = 0; t < T; t += 4) {
                float w0 = Qt[t * 17 + ql];
                float w1 = Qt[(t + 1) * 17 + ql];
                float w2 = Qt[(t + 2) * 17 + ql];
                float w3 = Qt[(t + 3) * 17 + ql];
                float4 u0 = Ug[t * 16];
                float4 u1 = Ug[(t + 1) * 16];
                float4 u2 = Ug[(t + 2) * 16];
                float4 u3 = Ug[(t + 3) * 16];
                a0.x += w0 * u0.x; a0.y += w0 * u0.y; a0.z += w0 * u0.z; a0.w += w0 * u0.w;
                a1.x += w1 * u1.x; a1.y += w1 * u1.y; a1.z += w1 * u1.z; a1.w += w1 * u1.w;
                a2.x += w2 * u2.x; a2.y += w2 * u2.y; a2.z += w2 * u2.z; a2.w += w2 * u2.w;
                a3.x += w3 * u3.x; a3.y += w3 * u3.y; a3.z += w3 * u3.z; a3.w += w3 * u3.w;
            }
            float inv = 1.0f / Dqs[ql];
            float4 acc;
            acc.x = ((a0.x + a1.x) + (a2.x + a3.x)) * inv;
            acc.y = ((a0.y + a1.y) + (a2.y + a3.y)) * inv;
            acc.z = ((a0.z + a1.z) + (a2.z + a3.z)) * inv;
            acc.w = ((a0.w + a1.w) + (a2.w + a3.w)) * inv;
            reinterpret_cast<float4*>(out + Z_OFF)[(n * S + q0 + ql) * 16 + hq] = acc;
        }
    } else if (b < 96 + VG_BLOCKS) {
        // ---------------- vgated tile writer ----------------
        // block = (n, s-chunk 16, t-chunk 16); stage sv1+v2 rows once.
        float4* sv = reinterpret_cast<float4*>(sm);        // 256 f4
        float4* vv = reinterpret_cast<float4*>(sm) + 256;  // 256 f4
        int idx = b - 96;
        int tc = idx % 12;
        int r2 = idx / 12;
        int sc = r2 % 12, n = r2 / 12;
        int s0 = sc * 16, t0 = tc * 16;
        int ry = tid >> 4, rx = tid & 15;
        sv[tid] = reinterpret_cast<const float4*>(g_sv1)[(n * S + s0 + ry) * 16 + rx];
        vv[tid] = reinterpret_cast<const float4*>(v2)[(n * S + t0 + ry) * 16 + rx];
        __syncthreads();
        float4 b4 = vv[ry * 16 + rx];   // ry = t-local, rx = h4
        float4* dst = reinterpret_cast<float4*>(out + VG_OFF)
                      + ((unsigned)(n * S + s0) * S + t0 + ry) * 16 + rx;
#pragma unroll
        for (int sl = 0; sl < 16; sl++) {
            float4 a4 = sv[sl * 16 + rx];
            float4 o;
            o.x = a4.x * b4.x;
            o.y = a4.y * b4.y;
            o.z = a4.z * b4.z;
            o.w = a4.w * b4.w;
            dst[sl * (S * 16)] = o;
        }
    } else {
        // ---------------- score row writer ----------------
        // block = (n, t, s-chunk 16); qk row + kk column staged once.
        float* qks = sm;        // 192
        float* kks = sm + 192;  // 16
        int idx = b - 96 - VG_BLOCKS;
        int t = idx % S;
        int r2 = idx / S;
        int sc = r2 % 12, n = r2 / 12;
        int s0 = sc * 16;
        if (tid < 48)
            reinterpret_cast<float4*>(qks)[tid] =
                reinterpret_cast<const float4*>(g_qk)[(unsigned)(n * S + t) * 48 + tid];
        if (tid >= 64 && tid < 80)
            kks[tid - 64] = g_kk[(unsigned)(n * S + s0 + tid - 64) * S + t];
        __syncthreads();
        int ty = tid >> 4, tx = tid & 15;
        int s = s0 + ty;
        float kkv = kks[ty];
        bool rowmask = (s > t);
        float4* dst = reinterpret_cast<float4*>(out + SCORE_OFF)
                      + ((unsigned)(n * S + s) * S + t) * 48;
#pragma unroll
        for (int c = 0; c < 3; c++) {
            int q4 = tx + 16 * c;
            float4 qv = reinterpret_cast<float4*>(qks)[q4];
            int q0 = q4 * 4;
            float4 o;
            o.x = (rowmask || t > q0)     ? -1000000.0f : kkv + qv.x;
            o.y = (rowmask || t > q0 + 1) ? -1000000.0f : kkv + qv.y;
            o.z = (rowmask || t > q0 + 2) ? -1000000.0f : kkv + qv.z;
            o.w = (rowmask || t > q0 + 3) ? -1000000.0f : kkv + qv.w;
            dst[q4] = o;
        }
    }
}

extern "C" void kernel_launch(void* const* d_in, const int* in_sizes, int n_in,
                              void* d_out, int out_size) {
    const float* q  = (const float*)d_in[0];
    const float* k1 = (const float*)d_in[1];
    const float* k2 = (const float*)d_in[2];
    const float* v1 = (const float*)d_in[3];
    const float* v2 = (const float*)d_in[4];
    float* out = (float*)d_out;

    cudaFuncSetAttribute(megaA, cudaFuncAttributeMaxDynamicSharedMemorySize,
                         A_SMEM_FLOATS * sizeof(float));
    cudaFuncSetAttribute(megaB, cudaFuncAttributeMaxDynamicSharedMemorySize,
                         B_SMEM_FLOATS * sizeof(float));

    // A: z1 (inline silu) + both gemms + silu writer  (all independent)
    megaA<<<684, 256, A_SMEM_FLOATS * sizeof(float)>>>(q, k1, k2, v1, v2);

    // B: z2 + vgated + score  (depend only on A outputs)
    megaB<<<96 + VG_BLOCKS + SCORE_BLOCKS, 256, B_SMEM_FLOATS * sizeof(float)>>>(
        k2, q, v2, out);
}